// round 15
// baseline (speedup 1.0000x reference)
#include <cuda_runtime.h>
#include <cstdint>

typedef unsigned int u32;
typedef unsigned long long u64;

#define BB 8
#define CIN 768
#define NP 4096
#define IC 128
#define MID 256
#define OC 20
#define NSEG 4
#define SEGJ 1024
#define SEGT 16

// folded weights
__device__ float g_wtpg[3*IC*CIN];
__device__ float g_Cf[OC*CIN];
__device__ float g_A[OC*IC];
__device__ float g_cvec[OC];
// pre-split folded weights, bf16 hi/lo planes [3][160][384]
__device__ u32 g_w_h[3*160*384];
__device__ u32 g_w_l[3*160*384];
// projections as bf16 hi/lo planes, [b][n][c] packed bf16x2
__device__ u32 g_th_h[BB*NP*64];
__device__ u32 g_th_l[BB*NP*64];
__device__ u32 g_ph_h[BB*NP*64];
__device__ u32 g_ph_l[BB*NP*64];
__device__ u32 g_g_h [BB*NP*64];
__device__ u32 g_g_l [BB*NP*64];
// attention partials: z = A@yhat [seg][b][tile][20][128], + per-q m,l
__device__ float g_pz[NSEG*BB*32*OC*128];
__device__ float g_pm[NSEG*BB*32*128];
__device__ float g_pl[NSEG*BB*32*128];
#define SEG_Z_STRIDE (BB*32*OC*128ull)
#define SEG_M_STRIDE (BB*32*128ull)

__device__ __forceinline__ float fexp(float x){
    x = fmaxf(x, -80.f);
    float t = x * 1.4426950408889634f;
    float f = t + 12582912.f;
    float k = f - 12582912.f;
    float r = t - k;
    float p = 1.3333558e-3f;
    p = fmaf(p, r, 9.6181291e-3f);
    p = fmaf(p, r, 5.5504109e-2f);
    p = fmaf(p, r, 2.4022651e-1f);
    p = fmaf(p, r, 6.9314718e-1f);
    p = fmaf(p, r, 1.f);
    int ki = (int)k;
    return p * __int_as_float((ki + 127) << 23);
}

__device__ __forceinline__ u32 cvtbf2(float a, float b){
    u32 r; asm("cvt.rn.bf16x2.f32 %0, %1, %2;" : "=r"(r) : "f"(b), "f"(a)); return r;
}
__device__ __forceinline__ float blo(u32 u){ return __uint_as_float(u << 16); }
__device__ __forceinline__ float bhi(u32 u){ return __uint_as_float(u & 0xffff0000u); }

__device__ __forceinline__ void ffma2(u64& d, u64 a, u64 b){
    asm("fma.rn.f32x2 %0, %1, %2, %0;" : "+l"(d) : "l"(a), "l"(b));
}
__device__ __forceinline__ float2 u2f(u64 v){
    float2 r; asm("mov.b64 {%0,%1}, %2;" : "=f"(r.x), "=f"(r.y) : "l"(v)); return r;
}

__device__ __forceinline__ u32 smem_u32(const void* p){
    u32 a; asm("{ .reg .u64 t; cvta.to.shared.u64 t, %1; cvt.u32.u64 %0, t; }" : "=r"(a) : "l"(p)); return a;
}

// ---------------- mma / ldmatrix ----------------
__device__ __forceinline__ void mma16816(float* d, const u32* a, u32 b0, u32 b1){
    asm volatile("mma.sync.aligned.m16n8k16.row.col.f32.bf16.bf16.f32 "
        "{%0,%1,%2,%3}, {%4,%5,%6,%7}, {%8,%9}, {%0,%1,%2,%3};"
        : "+f"(d[0]), "+f"(d[1]), "+f"(d[2]), "+f"(d[3])
        : "r"(a[0]), "r"(a[1]), "r"(a[2]), "r"(a[3]), "r"(b0), "r"(b1));
}
__device__ __forceinline__ void ldsm4(u32* r, u32 addr){
    asm volatile("ldmatrix.sync.aligned.m8n8.x4.shared.b16 {%0,%1,%2,%3}, [%4];"
        : "=r"(r[0]), "=r"(r[1]), "=r"(r[2]), "=r"(r[3]) : "r"(addr));
}
__device__ __forceinline__ void ldsm4t(u32* r, u32 addr){
    asm volatile("ldmatrix.sync.aligned.m8n8.x4.trans.shared.b16 {%0,%1,%2,%3}, [%4];"
        : "=r"(r[0]), "=r"(r[1]), "=r"(r[2]), "=r"(r[3]) : "r"(addr));
}

__device__ __forceinline__ u32 sw16(u32 base, int row, int ch){
    return base + (u32)row*256u + (u32)((ch ^ (row & 7)) * 16);
}
__device__ __forceinline__ u32 sw8(u32 base, int row, int ch){
    return base + (u32)row*128u + (u32)((ch ^ (row & 7)) * 16);
}

#define CP16(dst, src) asm volatile("cp.async.cg.shared.global [%0], [%1], 16;" :: "r"(dst), "l"(src) : "memory")
#define CP_COMMIT()    asm volatile("cp.async.commit_group;" ::: "memory")
#define CP_WAIT1()     asm volatile("cp.async.wait_group 1;" ::: "memory")
#define CP_WAIT0()     asm volatile("cp.async.wait_group 0;" ::: "memory")

// ---------------- prep: tiled weight fold (wc reused via smem row cache) ----------------
// block = 16 output rows x 256 cols; grid (3 colchunks, 26 rowchunks)
__global__ void __launch_bounds__(256) prep_fold(
    const float* __restrict__ wc, const float* __restrict__ wt,
    const float* __restrict__ wp, const float* __restrict__ wg,
    const float* __restrict__ wo)
{
    __shared__ float ws[16][MID];
    int t = threadIdx.x;
    int colc = blockIdx.x, rc = blockIdx.y;
    #pragma unroll
    for (int i = 0; i < 16; i++) {
        int e = t + i*256;
        int rl = e >> 8, m = e & 255;
        int grow = rc*16 + rl;
        float v = 0.f;
        if (grow < 384) {
            int which = grow >> 7, rr = grow & 127;
            const float* wsrc = (which == 0) ? wt : (which == 1) ? wp : wg;
            v = wsrc[rr*MID + m];
        } else if (grow < 404) {
            v = wo[(grow-384)*MID + m];
        }
        ws[rl][m] = v;
    }
    __syncthreads();
    int col = colc*256 + t;
    float acc[16];
    #pragma unroll
    for (int r = 0; r < 16; r++) acc[r] = 0.f;
    for (int m = 0; m < MID; m++) {
        float wcv = wc[(size_t)m*CIN + col];
        #pragma unroll
        for (int r = 0; r < 16; r++) acc[r] = fmaf(ws[r][m], wcv, acc[r]);
    }
    #pragma unroll
    for (int r = 0; r < 16; r++) {
        int grow = rc*16 + r;
        if (grow < 384)      g_wtpg[(size_t)grow*CIN + col] = acc[r];
        else if (grow < 404) g_Cf[(size_t)(grow-384)*CIN + col] = acc[r];
    }
}

__global__ void __launch_bounds__(256) prep_misc(
    const float* __restrict__ wW, const float* __restrict__ bW,
    const float* __restrict__ gam, const float* __restrict__ bet,
    const float* __restrict__ mean, const float* __restrict__ var,
    const float* __restrict__ wo, const float* __restrict__ bo)
{
    int idx = blockIdx.x*256 + threadIdx.x;
    if (idx < OC*IC) {
        int o = idx / IC, i = idx % IC;
        float acc = 0.f;
        for (int m = 0; m < MID; m++) {
            float inv = gam[m] * rsqrtf(var[m] + 1e-5f);
            acc = fmaf(wo[o*MID+m]*inv, wW[m*IC+i], acc);
        }
        g_A[idx] = acc;
        return;
    }
    int o = idx - OC*IC;
    if (o < OC) {
        float acc = bo[o];
        for (int m = 0; m < MID; m++) {
            float inv = gam[m] * rsqrtf(var[m] + 1e-5f);
            acc += wo[o*MID+m] * (bW[m]*inv + bet[m] - mean[m]*inv);
        }
        g_cvec[o] = acc;
    }
}

__global__ void __launch_bounds__(256) prep2_kernel()
{
    int gid = blockIdx.x*256 + threadIdx.x;
    if (gid >= 3*160*384) return;
    int which = gid / (160*384);
    int rem = gid % (160*384);
    int r = rem / 384, kk = rem % 384;
    float f0 = 0.f, f1 = 0.f;
    if (r < 128) {
        f0 = g_wtpg[(which*IC + r)*CIN + 2*kk];
        f1 = g_wtpg[(which*IC + r)*CIN + 2*kk + 1];
    } else if (which == 0 && r < 148) {
        f0 = g_Cf[(r-128)*CIN + 2*kk];
        f1 = g_Cf[(r-128)*CIN + 2*kk + 1];
    }
    u32 h = cvtbf2(f0, f1);
    g_w_h[gid] = h;
    g_w_l[gid] = cvtbf2(f0 - blo(h), f1 - bhi(h));
}

// ---------------- tensorized projections + fused residual ----------------
#define PJ_XRAW 81920
#define PJ_XH0  147456
#define PJ_TOTAL 212992
#define WBUF 40960
#define WPL  20480

__global__ void __launch_bounds__(256) proj_kernel(const float* __restrict__ x1,
                                                   const float* __restrict__ x2,
                                                   float* __restrict__ out)
{
    extern __shared__ char smc[];
    u32 sb = smem_u32(smc);
    int t = threadIdx.x, lane = t & 31, w = t >> 5;
    int n0 = blockIdx.x * 128;
    int which = blockIdx.y;
    int b = blockIdx.z;
    const float* xb = (which == 0 ? x1 : x2) + (size_t)b * CIN * NP;
    const u32* wbase_h = g_w_h + (size_t)which * 160 * 384;
    const u32* wbase_l = g_w_l + (size_t)which * 160 * 384;

    int la15 = lane & 15, la7 = lane & 7;
    int lahalf = (lane >> 3) & 1, laq = lane >> 4;

    float acc[16][4];
    #pragma unroll
    for (int n = 0; n < 16; n++)
        #pragma unroll
        for (int i = 0; i < 4; i++) acc[n][i] = 0.f;
    float accr[2][2][4];
    #pragma unroll
    for (int mt = 0; mt < 2; mt++)
        #pragma unroll
        for (int cp = 0; cp < 2; cp++)
            #pragma unroll
            for (int i = 0; i < 4; i++) accr[mt][cp][i] = 0.f;

    #define PJ_STAGE(c_) do { \
        int cur_ = (c_) & 1; int k0_ = (c_) * 64; \
        _Pragma("unroll") \
        for (int i = 0; i < 10; i++) { \
            int e = t + i*256; \
            int p = (i >= 5); \
            int rest = e - p*1280; \
            int ch = rest >> 3, q = rest & 7; \
            u32 dst = sb + (u32)cur_*WBUF + (u32)p*WPL + (u32)ch*128u + (u32)(((q ^ (ch & 7)))*16); \
            const u32* src = (p ? wbase_l : wbase_h) + (size_t)ch*384 + (k0_ >> 1) + q*4; \
            CP16(dst, src); \
        } \
        _Pragma("unroll") \
        for (int i = 0; i < 8; i++) { \
            int e = t + i*256; \
            int r = e >> 5, cc = e & 31; \
            u32 dst = sb + PJ_XRAW + (u32)cur_*32768u + (u32)r*512u + (u32)cc*16u; \
            const float* src = xb + (size_t)(k0_ + r)*NP + n0 + cc*4; \
            CP16(dst, src); \
        } \
        CP_COMMIT(); \
    } while(0)

    PJ_STAGE(0);
    for (int c = 0; c < 12; c++) {
        int cur = c & 1;
        CP_WAIT0();
        __syncthreads();
        if (c < 11) PJ_STAGE(c + 1);

        u32 xh = sb + PJ_XH0 + (u32)cur*32768u;
        u32 xl = xh + 16384u;
        #pragma unroll
        for (int i = 0; i < 8; i++) {
            int e = t + i*256;
            int k = e >> 5, nq = e & 31;
            float4 v = *(const float4*)(smc + PJ_XRAW + cur*32768 + k*512 + nq*16);
            u32 h0 = cvtbf2(v.x, v.y), h1 = cvtbf2(v.z, v.w);
            u32 l0 = cvtbf2(v.x - blo(h0), v.y - bhi(h0));
            u32 l1 = cvtbf2(v.z - blo(h1), v.w - bhi(h1));
            u32 off = (u32)k*256u + (u32)((((nq>>1) ^ (k&7)))*16) + (u32)((nq&1)*8);
            *(uint2*)(smc + (xh - sb) + off) = make_uint2(h0, h1);
            *(uint2*)(smc + (xl - sb) + off) = make_uint2(l0, l1);
        }
        __syncthreads();

        u32 wh = sb + (u32)cur*WBUF, wl = wh + WPL;
        #pragma unroll
        for (int ks = 0; ks < 4; ks++) {
            u32 ah[4], al[4];
            int ar = w*16 + la15, ach = 2*ks + laq;
            ldsm4(ah, sw8(wh, ar, ach));
            ldsm4(al, sw8(wl, ar, ach));
            int kr = ks*16 + lahalf*8 + la7;
            #pragma unroll
            for (int nn = 0; nn < 8; nn++) {
                int bch = 2*nn + laq;
                u32 bh[4], bl[4];
                ldsm4t(bh, sw16(xh, kr, bch));
                mma16816(acc[2*nn],   ah, bh[0], bh[1]);
                mma16816(acc[2*nn+1], ah, bh[2], bh[3]);
                mma16816(acc[2*nn],   al, bh[0], bh[1]);
                mma16816(acc[2*nn+1], al, bh[2], bh[3]);
                ldsm4t(bl, sw16(xl, kr, bch));
                mma16816(acc[2*nn],   ah, bl[0], bl[1]);
                mma16816(acc[2*nn+1], ah, bl[2], bl[3]);
            }
            if (which == 0) {
                u32 bhs[4], bls[4];
                ldsm4t(bhs, sw16(xh, kr, 2*w + laq));
                ldsm4t(bls, sw16(xl, kr, 2*w + laq));
                #pragma unroll
                for (int mt = 0; mt < 2; mt++) {
                    u32 arh[4], arl[4];
                    ldsm4(arh, sw8(wh, 128 + mt*16 + la15, ach));
                    ldsm4(arl, sw8(wl, 128 + mt*16 + la15, ach));
                    mma16816(accr[mt][0], arh, bhs[0], bhs[1]);
                    mma16816(accr[mt][1], arh, bhs[2], bhs[3]);
                    mma16816(accr[mt][0], arl, bhs[0], bhs[1]);
                    mma16816(accr[mt][1], arl, bhs[2], bhs[3]);
                    mma16816(accr[mt][0], arh, bls[0], bls[1]);
                    mma16816(accr[mt][1], arh, bls[2], bls[3]);
                }
            }
        }
    }
    #undef PJ_STAGE

    if (which == 0) {
        float* ob = out + (size_t)b*OC*NP + n0;
        #pragma unroll
        for (int mt = 0; mt < 2; mt++) {
            #pragma unroll
            for (int cp = 0; cp < 2; cp++) {
                int o0 = mt*16 + (lane >> 2);
                int o1 = o0 + 8;
                int col = w*16 + cp*8 + 2*(lane & 3);
                if (o0 < OC) {
                    ob[(size_t)o0*NP + col]     = accr[mt][cp][0] + g_cvec[o0];
                    ob[(size_t)o0*NP + col + 1] = accr[mt][cp][1] + g_cvec[o0];
                }
                if (o1 < OC) {
                    ob[(size_t)o1*NP + col]     = accr[mt][cp][2] + g_cvec[o1];
                    ob[(size_t)o1*NP + col + 1] = accr[mt][cp][3] + g_cvec[o1];
                }
            }
        }
    }

    __syncthreads();
    float* outS = (float*)smc;
    {
        int r = w*16 + (lane >> 2);
        #pragma unroll
        for (int nn = 0; nn < 16; nn++) {
            int n = nn*8 + 2*(lane & 3);
            outS[r*133 + n]         = acc[nn][0];
            outS[r*133 + n + 1]     = acc[nn][1];
            outS[(r+8)*133 + n]     = acc[nn][2];
            outS[(r+8)*133 + n + 1] = acc[nn][3];
        }
    }
    __syncthreads();

    u32* dh = (which==0 ? g_th_h : which==1 ? g_ph_h : g_g_h) + (size_t)b*NP*64;
    u32* dl = (which==0 ? g_th_l : which==1 ? g_ph_l : g_g_l) + (size_t)b*NP*64;
    {
        int n = t >> 1, half = t & 1;
        u32 hb[32], lb[32];
        #pragma unroll
        for (int p = 0; p < 32; p++) {
            int c = half*64 + 2*p;
            float f0 = outS[c*133 + n];
            float f1 = outS[(c+1)*133 + n];
            u32 h = cvtbf2(f0, f1);
            hb[p] = h;
            lb[p] = cvtbf2(f0 - blo(h), f1 - bhi(h));
        }
        u32* ph_ = dh + (size_t)(n0 + n)*64 + half*32;
        u32* pl_ = dl + (size_t)(n0 + n)*64 + half*32;
        #pragma unroll
        for (int q = 0; q < 8; q++) {
            *(uint4*)(ph_ + q*4) = make_uint4(hb[4*q], hb[4*q+1], hb[4*q+2], hb[4*q+3]);
            *(uint4*)(pl_ + q*4) = make_uint4(lb[4*q], lb[4*q+1], lb[4*q+2], lb[4*q+3]);
        }
    }
}

// ---------------- attention: 4-way key-split, fused A@yhat (f32x2 epilogue) ----------------
#define PH_H 0
#define PH_L 16384
#define G_H  32768
#define G_L  49152
#define BUFSZ 65536
#define S_TH_H 131072
#define S_TH_L 163840
#define S_PM   196608
#define S_PS   197632
#define S_TOTAL 198656

__device__ __forceinline__ void stage_plane_async(u32 sdst, const u32* __restrict__ src,
                                                  int rows, int t, int nthr){
    for (int idx = t; idx < rows*16; idx += nthr) {
        int r = idx >> 4, ch = idx & 15;
        CP16(sdst + (u32)r*256u + (u32)((ch ^ (r & 7)) * 16), src + (size_t)r*64 + ch*4);
    }
}

__global__ void __launch_bounds__(512) attn_mma_kernel()
{
    extern __shared__ char smc[];
    u32 sb = smem_u32(smc);
    int t = threadIdx.x, lane = t & 31, w = t >> 5;
    int wp = w >> 1, h = w & 1;
    int seg = blockIdx.y;
    int b = blockIdx.z;
    int n0 = blockIdx.x * 128;
    size_t bn = (size_t)b * NP;

    float* pm = (float*)(smc + S_PM);
    float* ps = (float*)(smc + S_PS);

    const u32* phh = g_ph_h + (bn + (size_t)seg*SEGJ)*64;
    const u32* phl = g_ph_l + (bn + (size_t)seg*SEGJ)*64;
    const u32* ggh = g_g_h  + (bn + (size_t)seg*SEGJ)*64;
    const u32* ggl = g_g_l  + (bn + (size_t)seg*SEGJ)*64;

    stage_plane_async(sb + S_TH_H, g_th_h + (bn + n0)*64, 128, t, 512);
    stage_plane_async(sb + S_TH_L, g_th_l + (bn + n0)*64, 128, t, 512);
    stage_plane_async(sb + PH_H, phh, 64, t, 512);
    stage_plane_async(sb + PH_L, phl, 64, t, 512);
    stage_plane_async(sb + G_H,  ggh, 64, t, 512);
    stage_plane_async(sb + G_L,  ggl, 64, t, 512);
    CP_COMMIT();
    {
        size_t jn = (size_t)64 * 64;
        stage_plane_async(sb + BUFSZ + PH_H, phh + jn, 64, t, 512);
        stage_plane_async(sb + BUFSZ + PH_L, phl + jn, 64, t, 512);
        stage_plane_async(sb + BUFSZ + G_H,  ggh + jn, 64, t, 512);
        stage_plane_async(sb + BUFSZ + G_L,  ggl + jn, 64, t, 512);
        CP_COMMIT();
    }

    float y[16][4];
    #pragma unroll
    for (int n = 0; n < 16; n++)
        #pragma unroll
        for (int i = 0; i < 4; i++) y[n][i] = 0.f;
    float m0 = 0.f, m1 = 0.f;
    float l0 = 0.f, l1 = 0.f;

    int la15 = lane & 15, la7 = lane & 7;
    int lahalf = (lane >> 3) & 1, laq = lane >> 4;
    int r0 = lane >> 2;
    int qg0 = wp*16 + r0, qg1 = qg0 + 8;

    for (int jt = 0; jt < SEGT; jt++) {
        int cur = jt & 1;
        u32 buf = sb + (u32)cur * BUFSZ;
        if (jt < SEGT-1) CP_WAIT1(); else CP_WAIT0();
        __syncthreads();

        float S[4][4];
        #pragma unroll
        for (int n = 0; n < 4; n++)
            #pragma unroll
            for (int i = 0; i < 4; i++) S[n][i] = 0.f;

        #pragma unroll
        for (int k = 0; k < 8; k++) {
            u32 ah[4], al[4];
            int ar = wp*16 + la15, ach = 2*k + laq;
            ldsm4(ah, sw16(sb + S_TH_H, ar, ach));
            ldsm4(al, sw16(sb + S_TH_L, ar, ach));
            #pragma unroll
            for (int n4 = 0; n4 < 2; n4++) {
                int br = h*32 + (n4*2 + laq)*8 + la7;
                int bch = 2*k + lahalf;
                u32 bh[4], bl[4];
                ldsm4(bh, sw16(buf + PH_H, br, bch));
                mma16816(S[2*n4],   ah, bh[0], bh[1]);
                mma16816(S[2*n4+1], ah, bh[2], bh[3]);
                mma16816(S[2*n4],   al, bh[0], bh[1]);
                mma16816(S[2*n4+1], al, bh[2], bh[3]);
                ldsm4(bl, sw16(buf + PH_L, br, bch));
                mma16816(S[2*n4],   ah, bl[0], bl[1]);
                mma16816(S[2*n4+1], ah, bl[2], bl[3]);
            }
        }

        if (jt == 0) {
            float tm0 = -1e30f, tm1 = -1e30f;
            #pragma unroll
            for (int n = 0; n < 4; n++) {
                tm0 = fmaxf(tm0, fmaxf(S[n][0], S[n][1]));
                tm1 = fmaxf(tm1, fmaxf(S[n][2], S[n][3]));
            }
            tm0 = fmaxf(tm0, __shfl_xor_sync(0xffffffffu, tm0, 1));
            tm0 = fmaxf(tm0, __shfl_xor_sync(0xffffffffu, tm0, 2));
            tm1 = fmaxf(tm1, __shfl_xor_sync(0xffffffffu, tm1, 1));
            tm1 = fmaxf(tm1, __shfl_xor_sync(0xffffffffu, tm1, 2));
            m0 = tm0; m1 = tm1;
        }

        #pragma unroll
        for (int n = 0; n < 4; n++) {
            S[n][0] = fexp(S[n][0] - m0);
            S[n][1] = fexp(S[n][1] - m0);
            S[n][2] = fexp(S[n][2] - m1);
            S[n][3] = fexp(S[n][3] - m1);
            l0 += S[n][0] + S[n][1];
            l1 += S[n][2] + S[n][3];
        }

        u32 ph_own[2][4], pl_own[2][4];
        #pragma unroll
        for (int kp = 0; kp < 2; kp++) {
            float* sa  = S[2*kp];
            float* sb2 = S[2*kp+1];
            u32 h0 = cvtbf2(sa[0], sa[1]);
            u32 h1 = cvtbf2(sa[2], sa[3]);
            u32 h2 = cvtbf2(sb2[0], sb2[1]);
            u32 h3 = cvtbf2(sb2[2], sb2[3]);
            ph_own[kp][0]=h0; ph_own[kp][1]=h1; ph_own[kp][2]=h2; ph_own[kp][3]=h3;
            pl_own[kp][0] = cvtbf2(sa[0]-blo(h0), sa[1]-bhi(h0));
            pl_own[kp][1] = cvtbf2(sa[2]-blo(h1), sa[3]-bhi(h1));
            pl_own[kp][2] = cvtbf2(sb2[0]-blo(h2), sb2[1]-bhi(h2));
            pl_own[kp][3] = cvtbf2(sb2[2]-blo(h3), sb2[3]-bhi(h3));
        }

        #pragma unroll
        for (int kp = 0; kp < 2; kp++) {
            int gr = h*32 + kp*16 + lahalf*8 + la7;
            #pragma unroll
            for (int n8 = 0; n8 < 8; n8++) {
                int gch = 2*n8 + laq;
                u32 gh[4], gl[4];
                ldsm4t(gh, sw16(buf + G_H, gr, gch));
                mma16816(y[2*n8],   ph_own[kp], gh[0], gh[1]);
                mma16816(y[2*n8+1], ph_own[kp], gh[2], gh[3]);
                mma16816(y[2*n8],   pl_own[kp], gh[0], gh[1]);
                mma16816(y[2*n8+1], pl_own[kp], gh[2], gh[3]);
                ldsm4t(gl, sw16(buf + G_L, gr, gch));
                mma16816(y[2*n8],   ph_own[kp], gl[0], gl[1]);
                mma16816(y[2*n8+1], ph_own[kp], gl[2], gl[3]);
            }
        }
        __syncthreads();

        if (jt < SEGT-2) {
            u32 nbuf = sb + (u32)cur * BUFSZ;
            size_t jn = (size_t)(jt + 2) * 64 * 64;
            stage_plane_async(nbuf + PH_H, phh + jn, 64, t, 512);
            stage_plane_async(nbuf + PH_L, phl + jn, 64, t, 512);
            stage_plane_async(nbuf + G_H,  ggh + jn, 64, t, 512);
            stage_plane_async(nbuf + G_L,  ggl + jn, 64, t, 512);
            CP_COMMIT();
        }
    }

    // ---- epilogue: pair-merge yhat (stride 130), z = A@yhat via f32x2, store z+m+l ----
    l0 += __shfl_xor_sync(0xffffffffu, l0, 1);
    l0 += __shfl_xor_sync(0xffffffffu, l0, 2);
    l1 += __shfl_xor_sync(0xffffffffu, l1, 1);
    l1 += __shfl_xor_sync(0xffffffffu, l1, 2);
    if ((lane & 3) == 0) {
        pm[h*128 + qg0] = m0; pm[h*128 + qg1] = m1;
        ps[h*128 + qg0] = l0; ps[h*128 + qg1] = l1;
    }
    float* ys = (float*)smc;
    float* As = (float*)(smc + S_TH_H);   // theta dead now
    __syncthreads();
    for (int i = t; i < OC*IC; i += 512) As[i] = g_A[i];
    float nm0 = fmaxf(pm[qg0], pm[128 + qg0]);
    float nm1 = fmaxf(pm[qg1], pm[128 + qg1]);
    float sc0 = fexp(m0 - nm0);
    float sc1 = fexp(m1 - nm1);
    size_t pbq = (size_t)seg*SEG_M_STRIDE + ((size_t)b*32 + blockIdx.x)*128;
    if (h == 0) {
        if ((lane & 3) == 0) {
            float lt0 = ps[qg0]*fexp(pm[qg0] - nm0) + ps[128 + qg0]*fexp(pm[128 + qg0] - nm0);
            float lt1 = ps[qg1]*fexp(pm[qg1] - nm1) + ps[128 + qg1]*fexp(pm[128 + qg1] - nm1);
            g_pm[pbq + qg0] = nm0;  g_pm[pbq + qg1] = nm1;
            g_pl[pbq + qg0] = lt0;  g_pl[pbq + qg1] = lt1;
        }
        #pragma unroll
        for (int n = 0; n < 16; n++) {
            int c = n*8 + 2*(lane & 3);
            *(float2*)&ys[qg0*130 + c] = make_float2(y[n][0]*sc0, y[n][1]*sc0);
            *(float2*)&ys[qg1*130 + c] = make_float2(y[n][2]*sc1, y[n][3]*sc1);
        }
    }
    __syncthreads();
    if (h == 1) {
        #pragma unroll
        for (int n = 0; n < 16; n++) {
            int c = n*8 + 2*(lane & 3);
            float2 v0 = *(float2*)&ys[qg0*130 + c];
            float2 v1 = *(float2*)&ys[qg1*130 + c];
            v0.x += y[n][0]*sc0;  v0.y += y[n][1]*sc0;
            v1.x += y[n][2]*sc1;  v1.y += y[n][3]*sc1;
            *(float2*)&ys[qg0*130 + c] = v0;
            *(float2*)&ys[qg1*130 + c] = v1;
        }
    }
    __syncthreads();
    float* pz = g_pz + (size_t)seg*SEG_Z_STRIDE + ((size_t)b*32 + blockIdx.x)*OC*128;
    #pragma unroll
    for (int i = 0; i < 5; i++) {
        int idx = t + i*512;
        int q = idx & 127, o = idx >> 7;
        const u64* yrow = (const u64*)(ys + q*130);
        const u64* arow = (const u64*)(As + o*IC);
        u64 acc2 = 0ull;
        #pragma unroll 16
        for (int cc = 0; cc < 64; cc++) ffma2(acc2, arow[cc], yrow[cc]);
        float2 p = u2f(acc2);
        pz[(size_t)o*128 + q] = p.x + p.y;
    }
}

// ---------------- merge: combine 4 key-segment z-partials ----------------
__global__ void __launch_bounds__(256) merge_kernel(float* __restrict__ out)
{
    __shared__ float wgt[NSEG][128];
    int t = threadIdx.x;
    int tile = blockIdx.x, b = blockIdx.y;
    size_t base = ((size_t)b*32 + tile);

    if (t < 128) {
        int q = t;
        float nm[NSEG], lv[NSEG];
        #pragma unroll
        for (int s = 0; s < NSEG; s++) {
            nm[s] = g_pm[(size_t)s*SEG_M_STRIDE + base*128 + q];
            lv[s] = g_pl[(size_t)s*SEG_M_STRIDE + base*128 + q];
        }
        float NM = fmaxf(fmaxf(nm[0], nm[1]), fmaxf(nm[2], nm[3]));
        float wv[NSEG], L = 0.f;
        #pragma unroll
        for (int s = 0; s < NSEG; s++) { wv[s] = fexp(nm[s] - NM); L += lv[s]*wv[s]; }
        float inv = 1.f / L;
        #pragma unroll
        for (int s = 0; s < NSEG; s++) wgt[s][q] = wv[s] * inv;
    }
    __syncthreads();

    float* ob = out + (size_t)b*OC*NP + tile*128;
    #pragma unroll
    for (int i = 0; i < 10; i++) {
        int idx = t + i*256;
        int q = idx & 127, o = idx >> 7;
        float acc = 0.f;
        #pragma unroll
        for (int s = 0; s < NSEG; s++)
            acc = fmaf(g_pz[(size_t)s*SEG_Z_STRIDE + base*OC*128 + (size_t)o*128 + q], wgt[s][q], acc);
        ob[(size_t)o*NP + q] += acc;
    }
}

extern "C" void kernel_launch(void* const* d_in, const int* in_sizes, int n_in,
                              void* d_out, int out_size)
{
    const float* x1     = (const float*)d_in[0];
    const float* x2     = (const float*)d_in[1];
    const float* w_conv = (const float*)d_in[2];
    const float* w_th   = (const float*)d_in[3];
    const float* w_ph   = (const float*)d_in[4];
    const float* w_g    = (const float*)d_in[5];
    const float* w_W    = (const float*)d_in[6];
    const float* b_W    = (const float*)d_in[7];
    const float* gam    = (const float*)d_in[8];
    const float* bet    = (const float*)d_in[9];
    const float* mean   = (const float*)d_in[10];
    const float* var    = (const float*)d_in[11];
    const float* w_out  = (const float*)d_in[12];
    const float* b_out  = (const float*)d_in[13];
    float* out = (float*)d_out;

    cudaFuncSetAttribute(attn_mma_kernel, cudaFuncAttributeMaxDynamicSharedMemorySize, S_TOTAL);
    cudaFuncSetAttribute(proj_kernel, cudaFuncAttributeMaxDynamicSharedMemorySize, PJ_TOTAL);

    prep_fold<<<dim3(3, 26), 256>>>(w_conv, w_th, w_ph, w_g, w_out);
    prep_misc<<<11, 256>>>(w_W, b_W, gam, bet, mean, var, w_out, b_out);
    prep2_kernel<<<720, 256>>>();
    proj_kernel<<<dim3(32, 3, BB), 256, PJ_TOTAL>>>(x1, x2, out);
    attn_mma_kernel<<<dim3(32, NSEG, BB), 512, S_TOTAL>>>();
    merge_kernel<<<dim3(32, BB), 256>>>(out);
}

// round 16
// speedup vs baseline: 1.0690x; 1.0690x over previous
#include <cuda_runtime.h>
#include <cstdint>

typedef unsigned int u32;
typedef unsigned long long u64;

#define BB 8
#define CIN 768
#define NP 4096
#define IC 128
#define MID 256
#define OC 20
#define NSEG 4
#define SEGJ 1024
#define SEGT 16

// folded weights
__device__ float g_wtpg[3*IC*CIN];
__device__ float g_Cf[OC*CIN];
__device__ float g_A[OC*IC];
__device__ float g_cvec[OC];
// pre-split folded weights, bf16 hi/lo planes [3][160][384]
__device__ u32 g_w_h[3*160*384];
__device__ u32 g_w_l[3*160*384];
// projections as bf16 hi/lo planes, [b][n][c] packed bf16x2
__device__ u32 g_th_h[BB*NP*64];
__device__ u32 g_th_l[BB*NP*64];
__device__ u32 g_ph_h[BB*NP*64];
__device__ u32 g_ph_l[BB*NP*64];
__device__ u32 g_g_h [BB*NP*64];
__device__ u32 g_g_l [BB*NP*64];
// attention partials: yhat [seg][b][tile][128q][128c], + per-q m,l
__device__ float g_py[NSEG*BB*32*16384];
__device__ float g_pm[NSEG*BB*32*128];
__device__ float g_pl[NSEG*BB*32*128];
#define SEG_Y_STRIDE (BB*32*16384ull)
#define SEG_M_STRIDE (BB*32*128ull)

__device__ __forceinline__ float fexp(float x){
    x = fmaxf(x, -80.f);
    float t = x * 1.4426950408889634f;
    float f = t + 12582912.f;
    float k = f - 12582912.f;
    float r = t - k;
    float p = 1.3333558e-3f;
    p = fmaf(p, r, 9.6181291e-3f);
    p = fmaf(p, r, 5.5504109e-2f);
    p = fmaf(p, r, 2.4022651e-1f);
    p = fmaf(p, r, 6.9314718e-1f);
    p = fmaf(p, r, 1.f);
    int ki = (int)k;
    return p * __int_as_float((ki + 127) << 23);
}

__device__ __forceinline__ u32 cvtbf2(float a, float b){
    u32 r; asm("cvt.rn.bf16x2.f32 %0, %1, %2;" : "=r"(r) : "f"(b), "f"(a)); return r;
}
__device__ __forceinline__ float blo(u32 u){ return __uint_as_float(u << 16); }
__device__ __forceinline__ float bhi(u32 u){ return __uint_as_float(u & 0xffff0000u); }

__device__ __forceinline__ u32 smem_u32(const void* p){
    u32 a; asm("{ .reg .u64 t; cvta.to.shared.u64 t, %1; cvt.u32.u64 %0, t; }" : "=r"(a) : "l"(p)); return a;
}

// ---------------- mma / ldmatrix ----------------
__device__ __forceinline__ void mma16816(float* d, const u32* a, u32 b0, u32 b1){
    asm volatile("mma.sync.aligned.m16n8k16.row.col.f32.bf16.bf16.f32 "
        "{%0,%1,%2,%3}, {%4,%5,%6,%7}, {%8,%9}, {%0,%1,%2,%3};"
        : "+f"(d[0]), "+f"(d[1]), "+f"(d[2]), "+f"(d[3])
        : "r"(a[0]), "r"(a[1]), "r"(a[2]), "r"(a[3]), "r"(b0), "r"(b1));
}
__device__ __forceinline__ void ldsm4(u32* r, u32 addr){
    asm volatile("ldmatrix.sync.aligned.m8n8.x4.shared.b16 {%0,%1,%2,%3}, [%4];"
        : "=r"(r[0]), "=r"(r[1]), "=r"(r[2]), "=r"(r[3]) : "r"(addr));
}
__device__ __forceinline__ void ldsm4t(u32* r, u32 addr){
    asm volatile("ldmatrix.sync.aligned.m8n8.x4.trans.shared.b16 {%0,%1,%2,%3}, [%4];"
        : "=r"(r[0]), "=r"(r[1]), "=r"(r[2]), "=r"(r[3]) : "r"(addr));
}

__device__ __forceinline__ u32 sw16(u32 base, int row, int ch){
    return base + (u32)row*256u + (u32)((ch ^ (row & 7)) * 16);
}
__device__ __forceinline__ u32 sw8(u32 base, int row, int ch){
    return base + (u32)row*128u + (u32)((ch ^ (row & 7)) * 16);
}

#define CP16(dst, src) asm volatile("cp.async.cg.shared.global [%0], [%1], 16;" :: "r"(dst), "l"(src) : "memory")
#define CP_COMMIT()    asm volatile("cp.async.commit_group;" ::: "memory")
#define CP_WAIT1()     asm volatile("cp.async.wait_group 1;" ::: "memory")
#define CP_WAIT0()     asm volatile("cp.async.wait_group 0;" ::: "memory")

// ---------------- prep ----------------
__global__ void __launch_bounds__(256) prep_kernel(
    const float* __restrict__ wc, const float* __restrict__ wt,
    const float* __restrict__ wp, const float* __restrict__ wg,
    const float* __restrict__ wW, const float* __restrict__ bW,
    const float* __restrict__ gam, const float* __restrict__ bet,
    const float* __restrict__ mean, const float* __restrict__ var,
    const float* __restrict__ wo, const float* __restrict__ bo)
{
    int gid = blockIdx.x*256 + threadIdx.x;
    if (gid < 3*IC*CIN) {
        int r = gid / CIN, k = gid % CIN;
        const float* ws = (r < IC) ? wt : (r < 2*IC) ? wp : wg;
        int rr = r & (IC-1);
        float acc = 0.f;
        for (int m = 0; m < MID; m++) acc = fmaf(ws[rr*MID+m], wc[m*CIN+k], acc);
        g_wtpg[gid] = acc;
        return;
    }
    int idx = gid - 3*IC*CIN;
    if (idx < OC*CIN) {
        int o = idx / CIN, k = idx % CIN;
        float acc = 0.f;
        for (int m = 0; m < MID; m++) acc = fmaf(wo[o*MID+m], wc[m*CIN+k], acc);
        g_Cf[o*CIN + k] = acc;
        return;
    }
    idx -= OC*CIN;
    if (idx < OC*IC) {
        int o = idx / IC, i = idx % IC;
        float acc = 0.f;
        for (int m = 0; m < MID; m++) {
            float inv = gam[m] * rsqrtf(var[m] + 1e-5f);
            acc = fmaf(wo[o*MID+m]*inv, wW[m*IC+i], acc);
        }
        g_A[idx] = acc;
        return;
    }
    idx -= OC*IC;
    if (idx < OC) {
        float acc = bo[idx];
        for (int m = 0; m < MID; m++) {
            float inv = gam[m] * rsqrtf(var[m] + 1e-5f);
            acc += wo[idx*MID+m] * (bW[m]*inv + bet[m] - mean[m]*inv);
        }
        g_cvec[idx] = acc;
    }
}

__global__ void __launch_bounds__(256) prep2_kernel()
{
    int gid = blockIdx.x*256 + threadIdx.x;
    if (gid >= 3*160*384) return;
    int which = gid / (160*384);
    int rem = gid % (160*384);
    int r = rem / 384, kk = rem % 384;
    float f0 = 0.f, f1 = 0.f;
    if (r < 128) {
        f0 = g_wtpg[(which*IC + r)*CIN + 2*kk];
        f1 = g_wtpg[(which*IC + r)*CIN + 2*kk + 1];
    } else if (which == 0 && r < 148) {
        f0 = g_Cf[(r-128)*CIN + 2*kk];
        f1 = g_Cf[(r-128)*CIN + 2*kk + 1];
    }
    u32 h = cvtbf2(f0, f1);
    g_w_h[gid] = h;
    g_w_l[gid] = cvtbf2(f0 - blo(h), f1 - bhi(h));
}

// ---------------- tensorized projections + fused residual ----------------
#define PJ_XRAW 81920
#define PJ_XH0  147456
#define PJ_TOTAL 212992
#define WBUF 40960
#define WPL  20480

__global__ void __launch_bounds__(256) proj_kernel(const float* __restrict__ x1,
                                                   const float* __restrict__ x2,
                                                   float* __restrict__ out)
{
    extern __shared__ char smc[];
    u32 sb = smem_u32(smc);
    int t = threadIdx.x, lane = t & 31, w = t >> 5;
    int n0 = blockIdx.x * 128;
    int which = blockIdx.y;
    int b = blockIdx.z;
    const float* xb = (which == 0 ? x1 : x2) + (size_t)b * CIN * NP;
    const u32* wbase_h = g_w_h + (size_t)which * 160 * 384;
    const u32* wbase_l = g_w_l + (size_t)which * 160 * 384;

    int la15 = lane & 15, la7 = lane & 7;
    int lahalf = (lane >> 3) & 1, laq = lane >> 4;

    float acc[16][4];
    #pragma unroll
    for (int n = 0; n < 16; n++)
        #pragma unroll
        for (int i = 0; i < 4; i++) acc[n][i] = 0.f;
    float accr[2][2][4];
    #pragma unroll
    for (int mt = 0; mt < 2; mt++)
        #pragma unroll
        for (int cp = 0; cp < 2; cp++)
            #pragma unroll
            for (int i = 0; i < 4; i++) accr[mt][cp][i] = 0.f;

    #define PJ_STAGE(c_) do { \
        int cur_ = (c_) & 1; int k0_ = (c_) * 64; \
        _Pragma("unroll") \
        for (int i = 0; i < 10; i++) { \
            int e = t + i*256; \
            int p = (i >= 5); \
            int rest = e - p*1280; \
            int ch = rest >> 3, q = rest & 7; \
            u32 dst = sb + (u32)cur_*WBUF + (u32)p*WPL + (u32)ch*128u + (u32)(((q ^ (ch & 7)))*16); \
            const u32* src = (p ? wbase_l : wbase_h) + (size_t)ch*384 + (k0_ >> 1) + q*4; \
            CP16(dst, src); \
        } \
        _Pragma("unroll") \
        for (int i = 0; i < 8; i++) { \
            int e = t + i*256; \
            int r = e >> 5, cc = e & 31; \
            u32 dst = sb + PJ_XRAW + (u32)cur_*32768u + (u32)r*512u + (u32)cc*16u; \
            const float* src = xb + (size_t)(k0_ + r)*NP + n0 + cc*4; \
            CP16(dst, src); \
        } \
        CP_COMMIT(); \
    } while(0)

    PJ_STAGE(0);
    for (int c = 0; c < 12; c++) {
        int cur = c & 1;
        CP_WAIT0();
        __syncthreads();
        if (c < 11) PJ_STAGE(c + 1);

        u32 xh = sb + PJ_XH0 + (u32)cur*32768u;
        u32 xl = xh + 16384u;
        #pragma unroll
        for (int i = 0; i < 8; i++) {
            int e = t + i*256;
            int k = e >> 5, nq = e & 31;
            float4 v = *(const float4*)(smc + PJ_XRAW + cur*32768 + k*512 + nq*16);
            u32 h0 = cvtbf2(v.x, v.y), h1 = cvtbf2(v.z, v.w);
            u32 l0 = cvtbf2(v.x - blo(h0), v.y - bhi(h0));
            u32 l1 = cvtbf2(v.z - blo(h1), v.w - bhi(h1));
            u32 off = (u32)k*256u + (u32)((((nq>>1) ^ (k&7)))*16) + (u32)((nq&1)*8);
            *(uint2*)(smc + (xh - sb) + off) = make_uint2(h0, h1);
            *(uint2*)(smc + (xl - sb) + off) = make_uint2(l0, l1);
        }
        __syncthreads();

        u32 wh = sb + (u32)cur*WBUF, wl = wh + WPL;
        #pragma unroll
        for (int ks = 0; ks < 4; ks++) {
            u32 ah[4], al[4];
            int ar = w*16 + la15, ach = 2*ks + laq;
            ldsm4(ah, sw8(wh, ar, ach));
            ldsm4(al, sw8(wl, ar, ach));
            int kr = ks*16 + lahalf*8 + la7;
            #pragma unroll
            for (int nn = 0; nn < 8; nn++) {
                int bch = 2*nn + laq;
                u32 bh[4], bl[4];
                ldsm4t(bh, sw16(xh, kr, bch));
                mma16816(acc[2*nn],   ah, bh[0], bh[1]);
                mma16816(acc[2*nn+1], ah, bh[2], bh[3]);
                mma16816(acc[2*nn],   al, bh[0], bh[1]);
                mma16816(acc[2*nn+1], al, bh[2], bh[3]);
                ldsm4t(bl, sw16(xl, kr, bch));
                mma16816(acc[2*nn],   ah, bl[0], bl[1]);
                mma16816(acc[2*nn+1], ah, bl[2], bl[3]);
            }
            if (which == 0) {
                u32 bhs[4], bls[4];
                ldsm4t(bhs, sw16(xh, kr, 2*w + laq));
                ldsm4t(bls, sw16(xl, kr, 2*w + laq));
                #pragma unroll
                for (int mt = 0; mt < 2; mt++) {
                    u32 arh[4], arl[4];
                    ldsm4(arh, sw8(wh, 128 + mt*16 + la15, ach));
                    ldsm4(arl, sw8(wl, 128 + mt*16 + la15, ach));
                    mma16816(accr[mt][0], arh, bhs[0], bhs[1]);
                    mma16816(accr[mt][1], arh, bhs[2], bhs[3]);
                    mma16816(accr[mt][0], arl, bhs[0], bhs[1]);
                    mma16816(accr[mt][1], arl, bhs[2], bhs[3]);
                    mma16816(accr[mt][0], arh, bls[0], bls[1]);
                    mma16816(accr[mt][1], arh, bls[2], bls[3]);
                }
            }
        }
    }
    #undef PJ_STAGE

    if (which == 0) {
        float* ob = out + (size_t)b*OC*NP + n0;
        #pragma unroll
        for (int mt = 0; mt < 2; mt++) {
            #pragma unroll
            for (int cp = 0; cp < 2; cp++) {
                int o0 = mt*16 + (lane >> 2);
                int o1 = o0 + 8;
                int col = w*16 + cp*8 + 2*(lane & 3);
                if (o0 < OC) {
                    ob[(size_t)o0*NP + col]     = accr[mt][cp][0] + g_cvec[o0];
                    ob[(size_t)o0*NP + col + 1] = accr[mt][cp][1] + g_cvec[o0];
                }
                if (o1 < OC) {
                    ob[(size_t)o1*NP + col]     = accr[mt][cp][2] + g_cvec[o1];
                    ob[(size_t)o1*NP + col + 1] = accr[mt][cp][3] + g_cvec[o1];
                }
            }
        }
    }

    __syncthreads();
    float* outS = (float*)smc;
    {
        int r = w*16 + (lane >> 2);
        #pragma unroll
        for (int nn = 0; nn < 16; nn++) {
            int n = nn*8 + 2*(lane & 3);
            outS[r*133 + n]         = acc[nn][0];
            outS[r*133 + n + 1]     = acc[nn][1];
            outS[(r+8)*133 + n]     = acc[nn][2];
            outS[(r+8)*133 + n + 1] = acc[nn][3];
        }
    }
    __syncthreads();

    u32* dh = (which==0 ? g_th_h : which==1 ? g_ph_h : g_g_h) + (size_t)b*NP*64;
    u32* dl = (which==0 ? g_th_l : which==1 ? g_ph_l : g_g_l) + (size_t)b*NP*64;
    {
        int n = t >> 1, half = t & 1;
        u32 hb[32], lb[32];
        #pragma unroll
        for (int p = 0; p < 32; p++) {
            int c = half*64 + 2*p;
            float f0 = outS[c*133 + n];
            float f1 = outS[(c+1)*133 + n];
            u32 h = cvtbf2(f0, f1);
            hb[p] = h;
            lb[p] = cvtbf2(f0 - blo(h), f1 - bhi(h));
        }
        u32* ph_ = dh + (size_t)(n0 + n)*64 + half*32;
        u32* pl_ = dl + (size_t)(n0 + n)*64 + half*32;
        #pragma unroll
        for (int q = 0; q < 8; q++) {
            *(uint4*)(ph_ + q*4) = make_uint4(hb[4*q], hb[4*q+1], hb[4*q+2], hb[4*q+3]);
            *(uint4*)(pl_ + q*4) = make_uint4(lb[4*q], lb[4*q+1], lb[4*q+2], lb[4*q+3]);
        }
    }
}

// ---------------- attention: 4-way key-split, partial yhat outputs ----------------
#define PH_H 0
#define PH_L 16384
#define G_H  32768
#define G_L  49152
#define BUFSZ 65536
#define S_TH_H 131072
#define S_TH_L 163840
#define S_PM   196608
#define S_PS   197632
#define S_TOTAL 198656

__device__ __forceinline__ void stage_plane_async(u32 sdst, const u32* __restrict__ src,
                                                  int rows, int t, int nthr){
    for (int idx = t; idx < rows*16; idx += nthr) {
        int r = idx >> 4, ch = idx & 15;
        CP16(sdst + (u32)r*256u + (u32)((ch ^ (r & 7)) * 16), src + (size_t)r*64 + ch*4);
    }
}

__global__ void __launch_bounds__(512) attn_mma_kernel()
{
    extern __shared__ char smc[];
    u32 sb = smem_u32(smc);
    int t = threadIdx.x, lane = t & 31, w = t >> 5;
    int wp = w >> 1, h = w & 1;
    int seg = blockIdx.y;
    int b = blockIdx.z;
    int n0 = blockIdx.x * 128;
    size_t bn = (size_t)b * NP;

    float* pm = (float*)(smc + S_PM);
    float* ps = (float*)(smc + S_PS);

    const u32* phh = g_ph_h + (bn + (size_t)seg*SEGJ)*64;
    const u32* phl = g_ph_l + (bn + (size_t)seg*SEGJ)*64;
    const u32* ggh = g_g_h  + (bn + (size_t)seg*SEGJ)*64;
    const u32* ggl = g_g_l  + (bn + (size_t)seg*SEGJ)*64;

    stage_plane_async(sb + S_TH_H, g_th_h + (bn + n0)*64, 128, t, 512);
    stage_plane_async(sb + S_TH_L, g_th_l + (bn + n0)*64, 128, t, 512);
    stage_plane_async(sb + PH_H, phh, 64, t, 512);
    stage_plane_async(sb + PH_L, phl, 64, t, 512);
    stage_plane_async(sb + G_H,  ggh, 64, t, 512);
    stage_plane_async(sb + G_L,  ggl, 64, t, 512);
    CP_COMMIT();
    {
        size_t jn = (size_t)64 * 64;
        stage_plane_async(sb + BUFSZ + PH_H, phh + jn, 64, t, 512);
        stage_plane_async(sb + BUFSZ + PH_L, phl + jn, 64, t, 512);
        stage_plane_async(sb + BUFSZ + G_H,  ggh + jn, 64, t, 512);
        stage_plane_async(sb + BUFSZ + G_L,  ggl + jn, 64, t, 512);
        CP_COMMIT();
    }

    float y[16][4];
    #pragma unroll
    for (int n = 0; n < 16; n++)
        #pragma unroll
        for (int i = 0; i < 4; i++) y[n][i] = 0.f;
    float m0 = 0.f, m1 = 0.f;
    float l0 = 0.f, l1 = 0.f;

    int la15 = lane & 15, la7 = lane & 7;
    int lahalf = (lane >> 3) & 1, laq = lane >> 4;
    int r0 = lane >> 2;
    int qg0 = wp*16 + r0, qg1 = qg0 + 8;

    for (int jt = 0; jt < SEGT; jt++) {
        int cur = jt & 1;
        u32 buf = sb + (u32)cur * BUFSZ;
        if (jt < SEGT-1) CP_WAIT1(); else CP_WAIT0();
        __syncthreads();

        float S[4][4];
        #pragma unroll
        for (int n = 0; n < 4; n++)
            #pragma unroll
            for (int i = 0; i < 4; i++) S[n][i] = 0.f;

        #pragma unroll
        for (int k = 0; k < 8; k++) {
            u32 ah[4], al[4];
            int ar = wp*16 + la15, ach = 2*k + laq;
            ldsm4(ah, sw16(sb + S_TH_H, ar, ach));
            ldsm4(al, sw16(sb + S_TH_L, ar, ach));
            #pragma unroll
            for (int n4 = 0; n4 < 2; n4++) {
                int br = h*32 + (n4*2 + laq)*8 + la7;
                int bch = 2*k + lahalf;
                u32 bh[4], bl[4];
                ldsm4(bh, sw16(buf + PH_H, br, bch));
                mma16816(S[2*n4],   ah, bh[0], bh[1]);
                mma16816(S[2*n4+1], ah, bh[2], bh[3]);
                mma16816(S[2*n4],   al, bh[0], bh[1]);
                mma16816(S[2*n4+1], al, bh[2], bh[3]);
                ldsm4(bl, sw16(buf + PH_L, br, bch));
                mma16816(S[2*n4],   ah, bl[0], bl[1]);
                mma16816(S[2*n4+1], ah, bl[2], bl[3]);
            }
        }

        if (jt == 0) {
            float tm0 = -1e30f, tm1 = -1e30f;
            #pragma unroll
            for (int n = 0; n < 4; n++) {
                tm0 = fmaxf(tm0, fmaxf(S[n][0], S[n][1]));
                tm1 = fmaxf(tm1, fmaxf(S[n][2], S[n][3]));
            }
            tm0 = fmaxf(tm0, __shfl_xor_sync(0xffffffffu, tm0, 1));
            tm0 = fmaxf(tm0, __shfl_xor_sync(0xffffffffu, tm0, 2));
            tm1 = fmaxf(tm1, __shfl_xor_sync(0xffffffffu, tm1, 1));
            tm1 = fmaxf(tm1, __shfl_xor_sync(0xffffffffu, tm1, 2));
            m0 = tm0; m1 = tm1;
        }

        #pragma unroll
        for (int n = 0; n < 4; n++) {
            S[n][0] = fexp(S[n][0] - m0);
            S[n][1] = fexp(S[n][1] - m0);
            S[n][2] = fexp(S[n][2] - m1);
            S[n][3] = fexp(S[n][3] - m1);
            l0 += S[n][0] + S[n][1];
            l1 += S[n][2] + S[n][3];
        }

        u32 ph_own[2][4], pl_own[2][4];
        #pragma unroll
        for (int kp = 0; kp < 2; kp++) {
            float* sa  = S[2*kp];
            float* sb2 = S[2*kp+1];
            u32 h0 = cvtbf2(sa[0], sa[1]);
            u32 h1 = cvtbf2(sa[2], sa[3]);
            u32 h2 = cvtbf2(sb2[0], sb2[1]);
            u32 h3 = cvtbf2(sb2[2], sb2[3]);
            ph_own[kp][0]=h0; ph_own[kp][1]=h1; ph_own[kp][2]=h2; ph_own[kp][3]=h3;
            pl_own[kp][0] = cvtbf2(sa[0]-blo(h0), sa[1]-bhi(h0));
            pl_own[kp][1] = cvtbf2(sa[2]-blo(h1), sa[3]-bhi(h1));
            pl_own[kp][2] = cvtbf2(sb2[0]-blo(h2), sb2[1]-bhi(h2));
            pl_own[kp][3] = cvtbf2(sb2[2]-blo(h3), sb2[3]-bhi(h3));
        }

        #pragma unroll
        for (int kp = 0; kp < 2; kp++) {
            int gr = h*32 + kp*16 + lahalf*8 + la7;
            #pragma unroll
            for (int n8 = 0; n8 < 8; n8++) {
                int gch = 2*n8 + laq;
                u32 gh[4], gl[4];
                ldsm4t(gh, sw16(buf + G_H, gr, gch));
                mma16816(y[2*n8],   ph_own[kp], gh[0], gh[1]);
                mma16816(y[2*n8+1], ph_own[kp], gh[2], gh[3]);
                mma16816(y[2*n8],   pl_own[kp], gh[0], gh[1]);
                mma16816(y[2*n8+1], pl_own[kp], gh[2], gh[3]);
                ldsm4t(gl, sw16(buf + G_L, gr, gch));
                mma16816(y[2*n8],   ph_own[kp], gl[0], gl[1]);
                mma16816(y[2*n8+1], ph_own[kp], gl[2], gl[3]);
            }
        }
        __syncthreads();

        if (jt < SEGT-2) {
            u32 nbuf = sb + (u32)cur * BUFSZ;
            size_t jn = (size_t)(jt + 2) * 64 * 64;
            stage_plane_async(nbuf + PH_H, phh + jn, 64, t, 512);
            stage_plane_async(nbuf + PH_L, phl + jn, 64, t, 512);
            stage_plane_async(nbuf + G_H,  ggh + jn, 64, t, 512);
            stage_plane_async(nbuf + G_L,  ggl + jn, 64, t, 512);
            CP_COMMIT();
        }
    }

    // ---- epilogue: pair-merge into unnormalized partial, write to gmem ----
    l0 += __shfl_xor_sync(0xffffffffu, l0, 1);
    l0 += __shfl_xor_sync(0xffffffffu, l0, 2);
    l1 += __shfl_xor_sync(0xffffffffu, l1, 1);
    l1 += __shfl_xor_sync(0xffffffffu, l1, 2);
    if ((lane & 3) == 0) {
        pm[h*128 + qg0] = m0; pm[h*128 + qg1] = m1;
        ps[h*128 + qg0] = l0; ps[h*128 + qg1] = l1;
    }
    float* ys = (float*)smc;
    __syncthreads();
    float nm0 = fmaxf(pm[qg0], pm[128 + qg0]);
    float nm1 = fmaxf(pm[qg1], pm[128 + qg1]);
    float sc0 = fexp(m0 - nm0);
    float sc1 = fexp(m1 - nm1);
    size_t pbq = (size_t)seg*SEG_M_STRIDE + ((size_t)b*32 + blockIdx.x)*128;
    if (h == 0) {
        if ((lane & 3) == 0) {
            float lt0 = ps[qg0]*fexp(pm[qg0] - nm0) + ps[128 + qg0]*fexp(pm[128 + qg0] - nm0);
            float lt1 = ps[qg1]*fexp(pm[qg1] - nm1) + ps[128 + qg1]*fexp(pm[128 + qg1] - nm1);
            g_pm[pbq + qg0] = nm0;  g_pm[pbq + qg1] = nm1;
            g_pl[pbq + qg0] = lt0;  g_pl[pbq + qg1] = lt1;
        }
        #pragma unroll
        for (int n = 0; n < 16; n++) {
            int c = n*8 + 2*(lane & 3);
            ys[qg0*129 + c]     = y[n][0] * sc0;
            ys[qg0*129 + c + 1] = y[n][1] * sc0;
            ys[qg1*129 + c]     = y[n][2] * sc1;
            ys[qg1*129 + c + 1] = y[n][3] * sc1;
        }
    }
    __syncthreads();
    if (h == 1) {
        #pragma unroll
        for (int n = 0; n < 16; n++) {
            int c = n*8 + 2*(lane & 3);
            ys[qg0*129 + c]     += y[n][0] * sc0;
            ys[qg0*129 + c + 1] += y[n][1] * sc0;
            ys[qg1*129 + c]     += y[n][2] * sc1;
            ys[qg1*129 + c + 1] += y[n][3] * sc1;
        }
    }
    __syncthreads();
    float* py = g_py + (size_t)seg*SEG_Y_STRIDE + ((size_t)b*32 + blockIdx.x)*16384;
    #pragma unroll
    for (int i = 0; i < 8; i++) {
        int idx4 = t + i*512;
        int qq = idx4 >> 5, c = (idx4 & 31)*4;
        float4 v = make_float4(ys[qq*129+c], ys[qq*129+c+1], ys[qq*129+c+2], ys[qq*129+c+3]);
        *(float4*)(py + (size_t)qq*128 + c) = v;
    }
}

// ---------------- merge: 4x-parallel (q-sliced) segment combine + A@y ----------------
__global__ void __launch_bounds__(256) merge_kernel(float* __restrict__ out)
{
    __shared__ float ys[32*129];
    __shared__ float As[OC*IC];
    __shared__ float wgt[NSEG][32];
    int t = threadIdx.x;
    int bx = blockIdx.x;           // 0..127
    int tile = bx >> 2, qc = bx & 3;
    int b = blockIdx.y;
    size_t base = ((size_t)b*32 + tile);

    for (int i = t; i < OC*IC; i += 256) As[i] = g_A[i];

    if (t < 32) {
        int q = qc*32 + t;
        float nm[NSEG], lv[NSEG];
        #pragma unroll
        for (int s = 0; s < NSEG; s++) {
            nm[s] = g_pm[(size_t)s*SEG_M_STRIDE + base*128 + q];
            lv[s] = g_pl[(size_t)s*SEG_M_STRIDE + base*128 + q];
        }
        float NM = fmaxf(fmaxf(nm[0], nm[1]), fmaxf(nm[2], nm[3]));
        float wv[NSEG], L = 0.f;
        #pragma unroll
        for (int s = 0; s < NSEG; s++) { wv[s] = fexp(nm[s] - NM); L += lv[s]*wv[s]; }
        float inv = 1.f / L;
        #pragma unroll
        for (int s = 0; s < NSEG; s++) wgt[s][t] = wv[s] * inv;
    }
    __syncthreads();

    // combine: 32q x 128c slice
    #pragma unroll
    for (int i = 0; i < 4; i++) {
        int idx4 = t + i*256;                 // 0..1023
        int ql = idx4 >> 5, c = (idx4 & 31) * 4;
        size_t off = base*16384 + (size_t)(qc*32 + ql)*128 + c;
        float4 a4 = make_float4(0.f, 0.f, 0.f, 0.f);
        #pragma unroll
        for (int s = 0; s < NSEG; s++) {
            float4 v = *(const float4*)(g_py + (size_t)s*SEG_Y_STRIDE + off);
            float wv = wgt[s][ql];
            a4.x = fmaf(v.x, wv, a4.x);
            a4.y = fmaf(v.y, wv, a4.y);
            a4.z = fmaf(v.z, wv, a4.z);
            a4.w = fmaf(v.w, wv, a4.w);
        }
        ys[ql*129 + c]     = a4.x;
        ys[ql*129 + c + 1] = a4.y;
        ys[ql*129 + c + 2] = a4.z;
        ys[ql*129 + c + 3] = a4.w;
    }
    __syncthreads();

    // epilogue: out[o][q] += A@ys ; 640 outputs over 256 threads
    float* ob = out + (size_t)b*OC*NP + tile*128 + qc*32;
    #pragma unroll
    for (int i = 0; i < 3; i++) {
        int idx = t + i*256;
        if (idx < OC*32) {
            int ql = idx & 31, o = idx >> 5;
            float acc = 0.f;
            #pragma unroll 8
            for (int c = 0; c < IC; c++) acc = fmaf(As[o*IC+c], ys[ql*129+c], acc);
            ob[(size_t)o*NP + ql] += acc;
        }
    }
}

extern "C" void kernel_launch(void* const* d_in, const int* in_sizes, int n_in,
                              void* d_out, int out_size)
{
    const float* x1     = (const float*)d_in[0];
    const float* x2     = (const float*)d_in[1];
    const float* w_conv = (const float*)d_in[2];
    const float* w_th   = (const float*)d_in[3];
    const float* w_ph   = (const float*)d_in[4];
    const float* w_g    = (const float*)d_in[5];
    const float* w_W    = (const float*)d_in[6];
    const float* b_W    = (const float*)d_in[7];
    const float* gam    = (const float*)d_in[8];
    const float* bet    = (const float*)d_in[9];
    const float* mean   = (const float*)d_in[10];
    const float* var    = (const float*)d_in[11];
    const float* w_out  = (const float*)d_in[12];
    const float* b_out  = (const float*)d_in[13];
    float* out = (float*)d_out;

    cudaFuncSetAttribute(attn_mma_kernel, cudaFuncAttributeMaxDynamicSharedMemorySize, S_TOTAL);
    cudaFuncSetAttribute(proj_kernel, cudaFuncAttributeMaxDynamicSharedMemorySize, PJ_TOTAL);

    prep_kernel<<<1223, 256>>>(w_conv, w_th, w_ph, w_g, w_W, b_W, gam, bet, mean, var, w_out, b_out);
    prep2_kernel<<<720, 256>>>();
    proj_kernel<<<dim3(32, 3, BB), 256, PJ_TOTAL>>>(x1, x2, out);
    attn_mma_kernel<<<dim3(32, NSEG, BB), 512, S_TOTAL>>>();
    merge_kernel<<<dim3(128, BB), 256>>>(out);
}